// round 11
// baseline (speedup 1.0000x reference)
#include <cuda_runtime.h>

// SIREN fused inference for sm_103a — round 11 (k-packed FMA2, 16 warps).
// N=1e6, D=3, F=128, L=8, O=1. Fully fused; activations SMEM-resident.
//
// R10 ncu: fma=60.3%, occ=12.5% (2 warps/SMSP), issue=44.3% -> latency-bound.
// Fixes here:
//  - NT=512 (4 warps/SMSP) for LDS latency hiding.
//  - FMA2 operands packed ALONG K: activation layout [k/4][point][4] and
//    weight rows padded to 132 floats; one LDS.128 = two f32x2 operands.
//    Zero dup-MOVs. acc halves = even/odd-k partials, summed in epilogue.
//  - Each warp owns ONE 8-feature group -> weight loads are single-address
//    broadcasts (1 crossbar phase).
// Model/SM/k: fma 128 cyc (binding), crossbar 96 phases, issue ~63%.

#define OMEGA_F 30.0f
constexpr int F       = 128;
constexpr int TILE    = 128;   // points per CTA
constexpr int NT      = 512;   // 16 warps
constexpr int NLAYERS = 8;
constexpr int WQ      = 33;    // weight row stride in float4 (132 floats)

#define FMA2(d, a, b, c) \
    asm("fma.rn.f32x2 %0, %1, %2, %3;" : "=l"(d) : "l"(a), "l"(b), "l"(c))

__device__ __forceinline__ float2 upk(unsigned long long v) {
    float2 r;
    asm("mov.b64 {%0, %1}, %2;" : "=f"(r.x), "=f"(r.y) : "l"(v));
    return r;
}

// Activation buffers: float4 array [32 k-quads][128 points].
// Element (point p, feature/k c) lives at float4 index (c>>2)*128 + p, lane (c&3).

template <bool RES>
__device__ __forceinline__ void gemm_act(
    const float4* __restrict__ Src4,   // [32][128]
    float4* __restrict__ Dst4,         // [32][128]
    const float4* __restrict__ Ws4,    // [128][WQ]
    const float* __restrict__ bs,      // [F], pre-scaled by OMEGA
    float scale, float w_out, int PT, int FTb)
{
    const ulonglong2* S2 = reinterpret_cast<const ulonglong2*>(Src4);
    const ulonglong2* W2 = reinterpret_cast<const ulonglong2*>(Ws4);

    unsigned long long acc[4][8];
#pragma unroll
    for (int j = 0; j < 4; j++)
#pragma unroll
        for (int i = 0; i < 8; i++) acc[j][i] = 0ULL;

#pragma unroll 2
    for (int kq = 0; kq < 32; kq++) {
        ulonglong2 av[4];
#pragma unroll
        for (int j = 0; j < 4; j++)
            av[j] = S2[kq * 128 + PT + 32 * j];     // LDS.128, lanes contiguous
#pragma unroll
        for (int i = 0; i < 8; i++) {
            ulonglong2 wv = W2[(FTb + i) * WQ + kq]; // broadcast LDS.128
#pragma unroll
            for (int j = 0; j < 4; j++) {
                FMA2(acc[j][i], av[j].x, wv.x, acc[j][i]);  // k, k+1
                FMA2(acc[j][i], av[j].y, wv.y, acc[j][i]);  // k+2, k+3
            }
        }
    }

    const int row0 = (FTb >> 2) * 128;        // float4 row for features FTb..FTb+3
    const int row1 = row0 + 128;              // features FTb+4..FTb+7
#pragma unroll
    for (int j = 0; j < 4; j++) {
        int p = PT + 32 * j;
        float hv[8];
        if (RES) {
            float4 h0 = Dst4[row0 + p], h1 = Dst4[row1 + p];
            hv[0] = h0.x; hv[1] = h0.y; hv[2] = h0.z; hv[3] = h0.w;
            hv[4] = h1.x; hv[5] = h1.y; hv[6] = h1.z; hv[7] = h1.w;
        }
        float r[8];
#pragma unroll
        for (int i = 0; i < 8; i++) {
            float2 a = upk(acc[j][i]);
            float s = __sinf(fmaf(a.x + a.y, scale, bs[FTb + i]));
            if (RES) s = w_out * (hv[i] + s);
            r[i] = s;
        }
        Dst4[row0 + p] = make_float4(r[0], r[1], r[2], r[3]);
        Dst4[row1 + p] = make_float4(r[4], r[5], r[6], r[7]);
    }
}

__global__ void __launch_bounds__(NT, 1) siren_fused_kernel(
    const float* __restrict__ coords,
    const float* __restrict__ W_first, const float* __restrict__ b_first,
    const float* __restrict__ W1, const float* __restrict__ b1,
    const float* __restrict__ W2, const float* __restrict__ b2,
    const float* __restrict__ W_out, const float* __restrict__ b_out,
    float* __restrict__ out, int N)
{
    extern __shared__ float4 smem4[];
    float4* Hs4 = smem4;                    // [32][128] running activation h
    float4* Ss4 = Hs4 + 32 * 128;           // [32][128] intermediate s1
    float4* Ws4 = Ss4 + 32 * 128;           // [128][WQ] padded weight tile
    float*  bs  = (float*)(Ws4 + F * WQ);   // [F] bias (pre-scaled)
    float*  cs  = bs + F;                   // [TILE*3] coords / later W_out
    float*  wf  = cs + TILE * 3;            // [F*3] first-layer weights

    const int tid = threadIdx.x;
    const int PT  = tid & 31;          // points PT, PT+32, PT+64, PT+96
    const int FTb = (tid >> 5) * 8;    // one 8-feature group per warp
    const int base = blockIdx.x * TILE;

    // Stage coords (zero-pad past N) + first-layer params.
    for (int idx = tid; idx < TILE * 3; idx += NT) {
        int g = base * 3 + idx;
        cs[idx] = (g < N * 3) ? coords[g] : 0.0f;
    }
    for (int idx = tid; idx < F * 3; idx += NT) wf[idx] = W_first[idx];
    if (tid < F) bs[tid] = b_first[tid];
    __syncthreads();

    // First layer: h = sin(OMEGA*(W_first x + b_first)). Args ~+-47 -> sinf.
    {
        const int row0 = (FTb >> 2) * 128, row1 = row0 + 128;
#pragma unroll
        for (int j = 0; j < 4; j++) {
            int p = PT + 32 * j;
            float x = cs[p * 3], y = cs[p * 3 + 1], z = cs[p * 3 + 2];
            float r[8];
#pragma unroll
            for (int i = 0; i < 8; i++) {
                int f = FTb + i;
                float a = fmaf(wf[f * 3], x,
                          fmaf(wf[f * 3 + 1], y,
                          fmaf(wf[f * 3 + 2], z, bs[f])));
                r[i] = sinf(OMEGA_F * a);
            }
            Hs4[row0 + p] = make_float4(r[0], r[1], r[2], r[3]);
            Hs4[row1 + p] = make_float4(r[4], r[5], r[6], r[7]);
        }
    }

    // Residual blocks.
    for (int l = 0; l < NLAYERS; l++) {
        float sc1   = (l > 0) ? (OMEGA_F * 0.5f) : OMEGA_F;
        float w_out = (l == NLAYERS - 1) ? 0.5f : 1.0f;

        __syncthreads();
        {   // stage W1[l]: [f][32] float4 -> padded [f][WQ]
            const float4* src4 = reinterpret_cast<const float4*>(W1 + l * F * F);
            for (int idx = tid; idx < F * 32; idx += NT) {
                int f = idx >> 5, kq = idx & 31;
                Ws4[f * WQ + kq] = src4[idx];
            }
        }
        if (tid < F) bs[tid] = OMEGA_F * b1[l * F + tid];
        __syncthreads();
        gemm_act<false>(Hs4, Ss4, Ws4, bs, sc1, 1.0f, PT, FTb);

        __syncthreads();
        {
            const float4* src4 = reinterpret_cast<const float4*>(W2 + l * F * F);
            for (int idx = tid; idx < F * 32; idx += NT) {
                int f = idx >> 5, kq = idx & 31;
                Ws4[f * WQ + kq] = src4[idx];
            }
        }
        if (tid < F) bs[tid] = OMEGA_F * b2[l * F + tid];
        __syncthreads();
        // h = w_out*(h + sin(...)); each (f,p) cell uniquely owned -> no race.
        gemm_act<true>(Ss4, Hs4, Ws4, bs, OMEGA_F, w_out, PT, FTb);
    }

    // Output head: out[p] = h[p] . W_out + b_out (O == 1).
    __syncthreads();
    if (tid < F) cs[tid] = W_out[tid];   // reuse cs for W_out
    __syncthreads();
    if (tid < TILE) {
        int p = base + tid;
        if (p < N) {
            float sum = 0.0f;
            const float4* w4 = reinterpret_cast<const float4*>(cs);
#pragma unroll 8
            for (int kq = 0; kq < 32; kq++) {
                float4 v = Hs4[kq * 128 + tid];
                float4 w = w4[kq];
                sum = fmaf(v.x, w.x, fmaf(v.y, w.y, fmaf(v.z, w.z, fmaf(v.w, w.w, sum))));
            }
            out[p] = sum + b_out[0];
        }
    }
}

extern "C" void kernel_launch(void* const* d_in, const int* in_sizes, int n_in,
                              void* d_out, int out_size)
{
    const float* coords  = (const float*)d_in[0];
    const float* W_first = (const float*)d_in[1];
    const float* b_first = (const float*)d_in[2];
    const float* W1      = (const float*)d_in[3];
    const float* b1      = (const float*)d_in[4];
    const float* W2      = (const float*)d_in[5];
    const float* b2      = (const float*)d_in[6];
    const float* W_out   = (const float*)d_in[7];
    const float* b_out   = (const float*)d_in[8];
    float* out = (float*)d_out;

    int N = in_sizes[0] / 3;
    int blocks = (N + TILE - 1) / TILE;

    size_t smem_bytes = (size_t)(2 * 32 * 128 + F * WQ) * sizeof(float4)
                      + (size_t)(F + TILE * 3 + F * 3) * sizeof(float);

    cudaFuncSetAttribute(siren_fused_kernel,
                         cudaFuncAttributeMaxDynamicSharedMemorySize,
                         (int)smem_bytes);

    siren_fused_kernel<<<blocks, NT, smem_bytes>>>(
        coords, W_first, b_first, W1, b1, W2, b2, W_out, b_out, out, N);
}